// round 11
// baseline (speedup 1.0000x reference)
#include <cuda_runtime.h>
#include <math.h>
#include <stdint.h>

// ---------------- problem constants (fixed by setup_inputs) ----------------
#define SDIM   96
#define PD     98
#define PD2    (PD*PD)            // 9604
#define CELLS  (2*PD*PD*PD)       // 1882384  (slabs b=0,1)
#define SCAN_BPB 4096
#define NBLK   ((CELLS + SCAN_BPB - 1)/SCAN_BPB)   // 460
#define CELLS_PAD (NBLK*SCAN_BPB)                  // 1884160
#define NMAX   200704
#define CH     67
#define DD     32
#define KTOP   128
#define NBINS  (1<<20)
#define CANDCAP 4096
#define LSTRIDE 132

// ---------------- scratch (device globals; no allocation) ----------------
__device__ int   g_flags[CELLS_PAD];
__device__ int   g_prefix[CELLS_PAD];
__device__ int   g_blkSums[512];
__device__ int   g_blkOff[512];
__device__ int   g_cellSeg[CELLS];
__device__ int   g_vcell[CELLS];
__device__ int   g_nkey[NMAX];
__device__ int   g_seg[NMAX];
__device__ int   g_segKey[NMAX];
__device__ int   g_cnt[NMAX];
__device__ float g_vinvc[NMAX];
__device__ float2 g_fAB[NMAX];
__device__ float g_sumF[CH*NMAX];
__device__ float g_pooled[CH*NMAX];
__device__ float g_scoreGrid[CELLS];
__device__ int   g_nbr[27*NMAX];
__device__ int   g_nbrN[NMAX];
__device__ unsigned long long g_peaks[NMAX];
__device__ int   g_hist[NBINS];
__device__ int   g_chunkSums[1024];
__device__ unsigned long long g_cand[CANDCAP];
__device__ int   g_peakCount;
__device__ int   g_candCount;
__device__ int   g_T;
__device__ int   g_M;
__device__ int   g_topIdx[KTOP];
__device__ float g_desc[(KTOP+1)*DD];
__device__ float g_L[(size_t)NMAX*LSTRIDE];

// ---------------- kernels ----------------

// keys + voxel grid scatter + new-cell occupancy flags
__global__ void kKeys(const int* __restrict__ coords, const float* __restrict__ offs, int N) {
    int i = blockIdx.x*blockDim.x + threadIdx.x;
    if (i >= N) return;
    int b = coords[4*i+0], x = coords[4*i+1], y = coords[4*i+2], z = coords[4*i+3];
    int vkey = ((b*PD + x+1)*PD + y+1)*PD + z+1;
    g_vcell[vkey] = i;
    int nx = x + (int)offs[3*i+0];
    int ny = y + (int)offs[3*i+1];
    int nz = z + (int)offs[3*i+2];
    int nkey = ((b*PD + nx+1)*PD + ny+1)*PD + nz+1;
    g_nkey[i] = nkey;
    g_flags[nkey] = 1;
}

// per-block exclusive scan of flags (4096 cells/block)
__global__ void kBlockScan() {
    __shared__ int sh[1024];
    int t = threadIdx.x, blk = blockIdx.x;
    int base = blk*SCAN_BPB + t*4;
    int4 f = *(const int4*)&g_flags[base];
    int s1 = f.x + f.y, s2 = s1 + f.z, s3 = s2 + f.w;
    sh[t] = s3; __syncthreads();
    for (int off=1; off<1024; off<<=1) {
        int a = (t>=off) ? sh[t-off] : 0;
        __syncthreads();
        sh[t] += a;
        __syncthreads();
    }
    int excl = sh[t] - s3;
    *(int4*)&g_prefix[base] = make_int4(excl, excl+f.x, excl+s1, excl+s2);
    if (t == 1023) g_blkSums[blk] = sh[1023];
}

__global__ void kScanBlkSums() {
    __shared__ int sh[512];
    int t = threadIdx.x;
    int v = (t < NBLK) ? g_blkSums[t] : 0;
    sh[t] = v; __syncthreads();
    for (int off=1; off<512; off<<=1) {
        int a = (t>=off) ? sh[t-off] : 0;
        __syncthreads();
        sh[t] += a;
        __syncthreads();
    }
    if (t < NBLK) g_blkOff[t] = sh[t] - v;
    if (t == NBLK-1) g_M = sh[t];
}

__global__ void kFinalize() {
    int k = blockIdx.x*blockDim.x + threadIdx.x;
    if (k >= CELLS) return;
    int f = g_flags[k];
    int p = g_prefix[k] + g_blkOff[k >> 12];
    g_cellSeg[k] = f ? p : -1;
    if (f) g_segKey[p] = k;
}

__global__ void kSeg(int N) {
    int i = blockIdx.x*blockDim.x + threadIdx.x;
    if (i >= N) return;
    int s = g_cellSeg[g_nkey[i]];
    g_seg[i] = s;
    atomicAdd(&g_cnt[s], 1);
}

__global__ void kPerVoxel(const float* __restrict__ cs, int N) {
    int i = blockIdx.x*blockDim.x + threadIdx.x;
    if (i >= N) return;
    int cn = g_cnt[g_seg[i]];
    g_vinvc[i] = 1.0f / (float)cn;
    g_fAB[i] = make_float2(cs[i], (float)cn);
}

__global__ void kAccumF(const float* __restrict__ feats, int N) {
    long long tid = (long long)blockIdx.x*blockDim.x + threadIdx.x;
    if (tid >= (long long)N*CH) return;
    int i = (int)(tid / CH);
    int c = (int)(tid % CH);
    float v = feats[tid] * g_vinvc[i];
    atomicAdd(&g_sumF[c*NMAX + g_seg[i]], v);
}

__global__ void kNbr() {
    int s = blockIdx.x*blockDim.x + threadIdx.x;
    if (s >= g_M) return;
    int key = g_segKey[s];
    int n = 0;
    #pragma unroll
    for (int kk = 0; kk < 27; kk++) {
        int dx = kk/9 - 1, dy = (kk/3)%3 - 1, dz = kk%3 - 1;
        int j = g_cellSeg[key + dx*PD2 + dy*PD + dz];
        if (j >= 0) { g_nbr[n*NMAX + s] = j; n++; }
    }
    g_nbrN[s] = n;
}

__global__ void kPooled() {
    int s = blockIdx.x*blockDim.x + threadIdx.x;
    int c = blockIdx.y;
    if (s >= g_M) return;
    int n = g_nbrN[s];
    float acc = 0.f;
    for (int t2 = 0; t2 < n; t2++)
        acc += g_sumF[c*NMAX + g_nbr[t2*NMAX + s]];
    g_pooled[c*NMAX + s] = acc / (float)n;
}

__global__ void kMixer(const float* __restrict__ mW, const float* __restrict__ mB,
                       float* __restrict__ outRef) {
    __shared__ float sW[54];
    __shared__ float sB;
    int t = threadIdx.x;
    if (t < 54) sW[t] = mW[t];
    if (t == 0) sB = mB[0];
    __syncthreads();
    int k = blockIdx.x*blockDim.x + t;
    if (k >= CELLS) return;
    int i = g_vcell[k];
    if (i < 0) return;
    float mix = sB;
    #pragma unroll
    for (int kk = 0; kk < 27; kk++) {
        int dx = kk/9 - 1, dy = (kk/3)%3 - 1, dz = kk%3 - 1;
        int j = g_vcell[k + dx*PD2 + dy*PD + dz];
        if (j >= 0) {
            float2 f = g_fAB[j];
            mix += f.x*sW[2*kk] + f.y*sW[2*kk+1];
        }
    }
    float r = 1.0f / (1.0f + expf(-mix));
    outRef[i] = r;
    g_scoreGrid[k] = r;
}

__global__ void kPeak() {
    int k = blockIdx.x*blockDim.x + threadIdx.x;
    if (k >= CELLS) return;
    int i = g_vcell[k];
    if (i < 0) return;
    float s = g_scoreGrid[k];
    if (!(s > 0.1f)) return;
    const float NI = __int_as_float(0xff800000);
    float hm = NI;
    #pragma unroll
    for (int kk = 0; kk < 27; kk++) {
        int dx = kk/9 - 1, dy = (kk/3)%3 - 1, dz = kk%3 - 1;
        float v = g_scoreGrid[k + dx*PD2 + dy*PD + dz];
        hm = fmaxf(hm, (v > 0.1f) ? v : NI);
    }
    if (hm == s && s > 0.2f) {
        int pos = atomicAdd(&g_peakCount, 1);
        unsigned sb = __float_as_uint(s);
        g_peaks[pos] = ((unsigned long long)sb << 32) |
                       (unsigned long long)(0xFFFFFFFFu - (unsigned)i);
        atomicAdd(&g_hist[sb >> 12], 1);
    }
}

__global__ void kChunkSum() {
    __shared__ int sh[256];
    int blk = blockIdx.x, t = threadIdx.x;
    int a = 0;
    for (int u = t; u < 1024; u += 256) a += g_hist[blk*1024 + u];
    sh[t] = a; __syncthreads();
    for (int off = 128; off > 0; off >>= 1) {
        if (t < off) sh[t] += sh[t+off];
        __syncthreads();
    }
    if (t == 0) g_chunkSums[blk] = sh[0];
}

__global__ void kFindT() {
    __shared__ int sh[1024];
    __shared__ int cstar, accAbove;
    int t = threadIdx.x;
    sh[t] = g_chunkSums[t]; __syncthreads();
    for (int off=1; off<1024; off<<=1) {             // inclusive suffix scan
        int a = (t+off < 1024) ? sh[t+off] : 0;
        __syncthreads();
        sh[t] += a;
        __syncthreads();
    }
    int total = sh[0];
    if (total < KTOP) {
        if (t == 0) g_T = 0;
        return;
    }
    int nxt = (t < 1023) ? sh[t+1] : 0;
    if (sh[t] >= KTOP && nxt < KTOP) { cstar = t; accAbove = nxt; }
    __syncthreads();
    int c = cstar, A = accAbove;
    sh[t] = g_hist[c*1024 + t]; __syncthreads();
    for (int off=1; off<1024; off<<=1) {
        int a = (t+off < 1024) ? sh[t+off] : 0;
        __syncthreads();
        sh[t] += a;
        __syncthreads();
    }
    int tot2 = A + sh[t];
    int nxt2 = A + ((t < 1023) ? sh[t+1] : 0);
    if (tot2 >= KTOP && nxt2 < KTOP) g_T = c*1024 + t;
}

__global__ void kCompact() {
    int p = blockIdx.x*blockDim.x + threadIdx.x;
    if (p >= g_peakCount) return;
    unsigned long long key = g_peaks[p];
    if ((int)(((unsigned)(key >> 32)) >> 12) >= g_T) {
        int pos = atomicAdd(&g_candCount, 1);
        if (pos < CANDCAP) g_cand[pos] = key;
    }
}

__global__ void kSelect(float* __restrict__ outConf) {
    __shared__ unsigned long long sk[CANDCAP];
    int t = threadIdx.x;
    int nc = g_candCount; if (nc > CANDCAP) nc = CANDCAP;
    for (int i = t; i < CANDCAP; i += 1024) sk[i] = (i < nc) ? g_cand[i] : 0ULL;
    __syncthreads();
    for (int k = 2; k <= CANDCAP; k <<= 1) {
        for (int j = k >> 1; j > 0; j >>= 1) {
            for (int i = t; i < CANDCAP; i += 1024) {
                int ixj = i ^ j;
                if (ixj > i) {
                    bool up = ((i & k) == 0);
                    unsigned long long a = sk[i], b = sk[ixj];
                    if (up ? (a < b) : (a > b)) { sk[i] = b; sk[ixj] = a; }
                }
            }
            __syncthreads();
        }
    }
    if (t < KTOP) {
        unsigned long long key = sk[t];
        unsigned sb = (unsigned)(key >> 32);
        float sc = __uint_as_float(sb);
        int idx = (int)(0xFFFFFFFFu - (unsigned)key);
        bool valid = sc > 0.0f;
        outConf[t] = valid ? sc : 0.0f;
        g_topIdx[t] = valid ? idx : -1;
    }
}

__global__ void kPeakDesc(const float* __restrict__ bg, const float* __restrict__ Wd,
                          const float* __restrict__ outConf) {
    int k = blockIdx.x, d = threadIdx.x;
    if (k == 0) { g_desc[d] = bg[d]; return; }
    int kk = k - 1;
    float conf = outConf[kk];
    if (!(conf > 0.0f)) { g_desc[k*DD + d] = 0.0f; return; }
    int row = g_seg[g_topIdx[kk]];
    float a = 0.f;
    for (int c = 0; c < CH; c++)
        a = fmaf(g_pooled[c*NMAX + row], Wd[c*DD + d], a);
    g_desc[k*DD + d] = fmaxf(a, 0.0f) * conf;
}

__global__ void __launch_bounds__(128) kFusedL(const float* __restrict__ Wd) {
    __shared__ float sW[CH*DD];
    __shared__ float sD[(KTOP+1)*DD];
    int t = threadIdx.x;
    for (int i = t; i < CH*DD; i += 128) sW[i] = Wd[i];
    for (int i = t; i < (KTOP+1)*DD; i += 128) sD[i] = g_desc[i];
    __syncthreads();
    int s = blockIdx.x*128 + t;
    if (s >= g_M) return;
    float dd[DD];
    #pragma unroll
    for (int q = 0; q < DD; q++) dd[q] = 0.f;
    for (int c = 0; c < CH; c++) {
        float pc = g_pooled[c*NMAX + s];
        #pragma unroll
        for (int q = 0; q < DD; q++) dd[q] = fmaf(pc, sW[c*DD + q], dd[q]);
    }
    #pragma unroll
    for (int q = 0; q < DD; q++) dd[q] = fmaxf(dd[q], 0.f);
    float* Lr = g_L + (size_t)s*LSTRIDE;
    for (int j = 0; j <= KTOP; j++) {
        float a = 0.f;
        #pragma unroll
        for (int q = 0; q < DD; q++) a = fmaf(dd[q], sD[j*DD + q], a);
        Lr[j] = a;
    }
}

__global__ void kInstance(float* __restrict__ outInst, int N) {
    int w = (blockIdx.x*blockDim.x + threadIdx.x) >> 5;   // one warp per voxel
    int lane = threadIdx.x & 31;
    if (w >= N) return;
    int r = g_seg[g_seg[w]];
    const float* Lr = g_L + (size_t)r*LSTRIDE;
    float* o = outInst + (size_t)w*(KTOP+1);
    for (int t = lane; t < KTOP+1; t += 32) o[t] = Lr[t];
}

// ---------------- launch ----------------
extern "C" void kernel_launch(void* const* d_in, const int* in_sizes, int n_in,
                              void* d_out, int out_size) {
    const int*   coords = (const int*)  d_in[0];
    const float* feats  = (const float*)d_in[1];
    const float* cscore = (const float*)d_in[2];
    const float* offs   = (const float*)d_in[3];
    const float* bg     = (const float*)d_in[4];
    const float* Wd     = (const float*)d_in[5];
    const float* mW     = (const float*)d_in[6];
    const float* mB     = (const float*)d_in[7];
    float* out = (float*)d_out;
    const int N = in_sizes[0] / 4;

    void* p;
    cudaGetSymbolAddress(&p, g_flags);     cudaMemsetAsync(p, 0,    sizeof(int)*CELLS_PAD);
    cudaGetSymbolAddress(&p, g_vcell);     cudaMemsetAsync(p, 0xFF, sizeof(int)*CELLS);
    cudaGetSymbolAddress(&p, g_scoreGrid); cudaMemsetAsync(p, 0,    sizeof(float)*CELLS);
    cudaGetSymbolAddress(&p, g_cnt);       cudaMemsetAsync(p, 0,    sizeof(int)*NMAX);
    cudaGetSymbolAddress(&p, g_sumF);      cudaMemsetAsync(p, 0,    sizeof(float)*CH*NMAX);
    cudaGetSymbolAddress(&p, g_hist);      cudaMemsetAsync(p, 0,    sizeof(int)*NBINS);
    cudaGetSymbolAddress(&p, g_peakCount); cudaMemsetAsync(p, 0,    sizeof(int));
    cudaGetSymbolAddress(&p, g_candCount); cudaMemsetAsync(p, 0,    sizeof(int));

    int nb = (N + 255) / 256;
    kKeys<<<nb, 256>>>(coords, offs, N);
    kBlockScan<<<NBLK, 1024>>>();
    kScanBlkSums<<<1, 512>>>();
    kFinalize<<<(CELLS + 255)/256, 256>>>();
    kSeg<<<nb, 256>>>(N);
    kPerVoxel<<<nb, 256>>>(cscore, N);
    {
        long long tot = (long long)N * CH;
        kAccumF<<<(unsigned)((tot + 255)/256), 256>>>(feats, N);
    }
    kNbr<<<(NMAX + 255)/256, 256>>>();
    {
        dim3 g((NMAX + 255)/256, CH);
        kPooled<<<g, 256>>>();
    }
    kMixer<<<(CELLS + 255)/256, 256>>>(mW, mB, out);
    kPeak<<<(CELLS + 255)/256, 256>>>();
    kChunkSum<<<1024, 256>>>();
    kFindT<<<1, 1024>>>();
    kCompact<<<nb, 256>>>();
    kSelect<<<1, 1024>>>(out + N);
    kPeakDesc<<<KTOP+1, DD>>>(bg, Wd, out + N);
    kFusedL<<<(NMAX + 127)/128, 128>>>(Wd);
    kInstance<<<(N*32 + 255)/256, 256>>>(out + N + KTOP, N);
}

// round 12
// speedup vs baseline: 1.0187x; 1.0187x over previous
#include <cuda_runtime.h>
#include <math.h>
#include <stdint.h>

// ---------------- problem constants (fixed by setup_inputs) ----------------
#define SDIM   96
#define PD     98
#define PD2    (PD*PD)            // 9604
#define CELLS  (2*PD*PD*PD)       // 1882384  (slabs b=0,1)
#define SCAN_BPB 4096
#define NBLK   ((CELLS + SCAN_BPB - 1)/SCAN_BPB)   // 460
#define CELLS_PAD (NBLK*SCAN_BPB)                  // 1884160
#define NMAX   200704
#define CH     67
#define DD     32
#define KTOP   128
#define NBINS  (1<<20)
#define CANDCAP 4096
#define LSTRIDE 132

// ---------------- scratch (device globals; no allocation) ----------------
__device__ int   g_flags[CELLS_PAD];
__device__ int   g_prefix[CELLS_PAD];
__device__ int   g_blkSums[512];
__device__ int   g_blkOff[512];
__device__ int   g_cellSeg[CELLS];
__device__ int   g_vcell[CELLS];
__device__ int   g_nkey[NMAX];
__device__ int   g_seg[NMAX];
__device__ int   g_segKey[NMAX];
__device__ int   g_cnt[NMAX];
__device__ float g_vinvc[NMAX];
__device__ float2 g_fAB[NMAX];
__device__ float g_sumF[CH*NMAX];
__device__ float g_pooled[CH*NMAX];
__device__ float g_scoreGrid[CELLS];
__device__ int   g_nbr[27*NMAX];
__device__ int   g_nbrN[NMAX];
__device__ unsigned long long g_peaks[NMAX];
__device__ int   g_hist[NBINS];
__device__ int   g_chunkSums[1024];
__device__ unsigned long long g_cand[CANDCAP];
__device__ int   g_peakCount;
__device__ int   g_candCount;
__device__ int   g_T;
__device__ int   g_M;
__device__ int   g_topIdx[KTOP];
__device__ float g_desc[(KTOP+1)*DD];
__device__ float g_L[(size_t)NMAX*LSTRIDE];

// ---------------- kernels ----------------

// keys + voxel grid scatter + new-cell occupancy flags
__global__ void kKeys(const int* __restrict__ coords, const float* __restrict__ offs, int N) {
    int i = blockIdx.x*blockDim.x + threadIdx.x;
    if (i >= N) return;
    int b = coords[4*i+0], x = coords[4*i+1], y = coords[4*i+2], z = coords[4*i+3];
    int vkey = ((b*PD + x+1)*PD + y+1)*PD + z+1;
    g_vcell[vkey] = i;
    int nx = x + (int)offs[3*i+0];
    int ny = y + (int)offs[3*i+1];
    int nz = z + (int)offs[3*i+2];
    int nkey = ((b*PD + nx+1)*PD + ny+1)*PD + nz+1;
    g_nkey[i] = nkey;
    g_flags[nkey] = 1;
}

// per-block exclusive scan of flags (4096 cells/block)
__global__ void kBlockScan() {
    __shared__ int sh[1024];
    int t = threadIdx.x, blk = blockIdx.x;
    int base = blk*SCAN_BPB + t*4;
    int4 f = *(const int4*)&g_flags[base];
    int s1 = f.x + f.y, s2 = s1 + f.z, s3 = s2 + f.w;
    sh[t] = s3; __syncthreads();
    for (int off=1; off<1024; off<<=1) {
        int a = (t>=off) ? sh[t-off] : 0;
        __syncthreads();
        sh[t] += a;
        __syncthreads();
    }
    int excl = sh[t] - s3;
    *(int4*)&g_prefix[base] = make_int4(excl, excl+f.x, excl+s1, excl+s2);
    if (t == 1023) g_blkSums[blk] = sh[1023];
}

__global__ void kScanBlkSums() {
    __shared__ int sh[512];
    int t = threadIdx.x;
    int v = (t < NBLK) ? g_blkSums[t] : 0;
    sh[t] = v; __syncthreads();
    for (int off=1; off<512; off<<=1) {
        int a = (t>=off) ? sh[t-off] : 0;
        __syncthreads();
        sh[t] += a;
        __syncthreads();
    }
    if (t < NBLK) g_blkOff[t] = sh[t] - v;
    if (t == NBLK-1) g_M = sh[t];
}

__global__ void kFinalize() {
    int k = blockIdx.x*blockDim.x + threadIdx.x;
    if (k >= CELLS) return;
    int f = g_flags[k];
    int p = g_prefix[k] + g_blkOff[k >> 12];
    g_cellSeg[k] = f ? p : -1;
    if (f) g_segKey[p] = k;
}

__global__ void kSeg(int N) {
    int i = blockIdx.x*blockDim.x + threadIdx.x;
    if (i >= N) return;
    int s = g_cellSeg[g_nkey[i]];
    g_seg[i] = s;
    atomicAdd(&g_cnt[s], 1);
}

__global__ void kPerVoxel(const float* __restrict__ cs, int N) {
    int i = blockIdx.x*blockDim.x + threadIdx.x;
    if (i >= N) return;
    int cn = g_cnt[g_seg[i]];
    g_vinvc[i] = 1.0f / (float)cn;
    g_fAB[i] = make_float2(cs[i], (float)cn);
}

__global__ void kAccumF(const float* __restrict__ feats, int N) {
    long long tid = (long long)blockIdx.x*blockDim.x + threadIdx.x;
    if (tid >= (long long)N*CH) return;
    int i = (int)(tid / CH);
    int c = (int)(tid % CH);
    float v = feats[tid] * g_vinvc[i];
    atomicAdd(&g_sumF[c*NMAX + g_seg[i]], v);
}

__global__ void kNbr() {
    int s = blockIdx.x*blockDim.x + threadIdx.x;
    if (s >= g_M) return;
    int key = g_segKey[s];
    int n = 0;
    #pragma unroll
    for (int kk = 0; kk < 27; kk++) {
        int dx = kk/9 - 1, dy = (kk/3)%3 - 1, dz = kk%3 - 1;
        int j = g_cellSeg[key + dx*PD2 + dy*PD + dz];
        if (j >= 0) { g_nbr[n*NMAX + s] = j; n++; }
    }
    g_nbrN[s] = n;
}

__global__ void kPooled() {
    int s = blockIdx.x*blockDim.x + threadIdx.x;
    int c = blockIdx.y;
    if (s >= g_M) return;
    int n = g_nbrN[s];
    float acc = 0.f;
    for (int t2 = 0; t2 < n; t2++)
        acc += g_sumF[c*NMAX + g_nbr[t2*NMAX + s]];
    g_pooled[c*NMAX + s] = acc / (float)n;
}

__global__ void kMixer(const float* __restrict__ mW, const float* __restrict__ mB,
                       float* __restrict__ outRef) {
    __shared__ float sW[54];
    __shared__ float sB;
    int t = threadIdx.x;
    if (t < 54) sW[t] = mW[t];
    if (t == 0) sB = mB[0];
    __syncthreads();
    int k = blockIdx.x*blockDim.x + t;
    if (k >= CELLS) return;
    int i = g_vcell[k];
    if (i < 0) return;
    float mix = sB;
    #pragma unroll
    for (int kk = 0; kk < 27; kk++) {
        int dx = kk/9 - 1, dy = (kk/3)%3 - 1, dz = kk%3 - 1;
        int j = g_vcell[k + dx*PD2 + dy*PD + dz];
        if (j >= 0) {
            float2 f = g_fAB[j];
            mix += f.x*sW[2*kk] + f.y*sW[2*kk+1];
        }
    }
    float r = 1.0f / (1.0f + expf(-mix));
    outRef[i] = r;
    g_scoreGrid[k] = r;
}

__global__ void kPeak() {
    int k = blockIdx.x*blockDim.x + threadIdx.x;
    if (k >= CELLS) return;
    int i = g_vcell[k];
    if (i < 0) return;
    float s = g_scoreGrid[k];
    if (!(s > 0.1f)) return;
    const float NI = __int_as_float(0xff800000);
    float hm = NI;
    #pragma unroll
    for (int kk = 0; kk < 27; kk++) {
        int dx = kk/9 - 1, dy = (kk/3)%3 - 1, dz = kk%3 - 1;
        float v = g_scoreGrid[k + dx*PD2 + dy*PD + dz];
        hm = fmaxf(hm, (v > 0.1f) ? v : NI);
    }
    if (hm == s && s > 0.2f) {
        int pos = atomicAdd(&g_peakCount, 1);
        unsigned sb = __float_as_uint(s);
        g_peaks[pos] = ((unsigned long long)sb << 32) |
                       (unsigned long long)(0xFFFFFFFFu - (unsigned)i);
        atomicAdd(&g_hist[sb >> 12], 1);
    }
}

__global__ void kChunkSum() {
    __shared__ int sh[256];
    int blk = blockIdx.x, t = threadIdx.x;
    int a = 0;
    for (int u = t; u < 1024; u += 256) a += g_hist[blk*1024 + u];
    sh[t] = a; __syncthreads();
    for (int off = 128; off > 0; off >>= 1) {
        if (t < off) sh[t] += sh[t+off];
        __syncthreads();
    }
    if (t == 0) g_chunkSums[blk] = sh[0];
}

__global__ void kFindT() {
    __shared__ int sh[1024];
    __shared__ int cstar, accAbove;
    int t = threadIdx.x;
    sh[t] = g_chunkSums[t]; __syncthreads();
    for (int off=1; off<1024; off<<=1) {             // inclusive suffix scan
        int a = (t+off < 1024) ? sh[t+off] : 0;
        __syncthreads();
        sh[t] += a;
        __syncthreads();
    }
    int total = sh[0];
    if (total < KTOP) {
        if (t == 0) g_T = 0;
        return;
    }
    int nxt = (t < 1023) ? sh[t+1] : 0;
    if (sh[t] >= KTOP && nxt < KTOP) { cstar = t; accAbove = nxt; }
    __syncthreads();
    int c = cstar, A = accAbove;
    sh[t] = g_hist[c*1024 + t]; __syncthreads();
    for (int off=1; off<1024; off<<=1) {
        int a = (t+off < 1024) ? sh[t+off] : 0;
        __syncthreads();
        sh[t] += a;
        __syncthreads();
    }
    int tot2 = A + sh[t];
    int nxt2 = A + ((t < 1023) ? sh[t+1] : 0);
    if (tot2 >= KTOP && nxt2 < KTOP) g_T = c*1024 + t;
}

__global__ void kCompact() {
    int p = blockIdx.x*blockDim.x + threadIdx.x;
    if (p >= g_peakCount) return;
    unsigned long long key = g_peaks[p];
    if ((int)(((unsigned)(key >> 32)) >> 12) >= g_T) {
        int pos = atomicAdd(&g_candCount, 1);
        if (pos < CANDCAP) g_cand[pos] = key;
    }
}

__global__ void kSelect(float* __restrict__ outConf) {
    __shared__ unsigned long long sk[CANDCAP];
    int t = threadIdx.x;
    int nc = g_candCount; if (nc > CANDCAP) nc = CANDCAP;
    for (int i = t; i < CANDCAP; i += 1024) sk[i] = (i < nc) ? g_cand[i] : 0ULL;
    __syncthreads();
    for (int k = 2; k <= CANDCAP; k <<= 1) {
        for (int j = k >> 1; j > 0; j >>= 1) {
            for (int i = t; i < CANDCAP; i += 1024) {
                int ixj = i ^ j;
                if (ixj > i) {
                    bool up = ((i & k) == 0);
                    unsigned long long a = sk[i], b = sk[ixj];
                    if (up ? (a < b) : (a > b)) { sk[i] = b; sk[ixj] = a; }
                }
            }
            __syncthreads();
        }
    }
    if (t < KTOP) {
        unsigned long long key = sk[t];
        unsigned sb = (unsigned)(key >> 32);
        float sc = __uint_as_float(sb);
        int idx = (int)(0xFFFFFFFFu - (unsigned)key);
        bool valid = sc > 0.0f;
        outConf[t] = valid ? sc : 0.0f;
        g_topIdx[t] = valid ? idx : -1;
    }
}

__global__ void kPeakDesc(const float* __restrict__ bg, const float* __restrict__ Wd,
                          const float* __restrict__ outConf) {
    int k = blockIdx.x, d = threadIdx.x;
    if (k == 0) { g_desc[d] = bg[d]; return; }
    int kk = k - 1;
    float conf = outConf[kk];
    if (!(conf > 0.0f)) { g_desc[k*DD + d] = 0.0f; return; }
    int row = g_seg[g_topIdx[kk]];
    float a = 0.f;
    for (int c = 0; c < CH; c++)
        a = fmaf(g_pooled[c*NMAX + row], Wd[c*DD + d], a);
    g_desc[k*DD + d] = fmaxf(a, 0.0f) * conf;
}

__global__ void __launch_bounds__(128) kFusedL(const float* __restrict__ Wd) {
    __shared__ float sW[CH*DD];
    __shared__ float sD[(KTOP+1)*DD];
    int t = threadIdx.x;
    for (int i = t; i < CH*DD; i += 128) sW[i] = Wd[i];
    for (int i = t; i < (KTOP+1)*DD; i += 128) sD[i] = g_desc[i];
    __syncthreads();
    int s = blockIdx.x*128 + t;
    if (s >= g_M) return;
    float dd[DD];
    #pragma unroll
    for (int q = 0; q < DD; q++) dd[q] = 0.f;
    for (int c = 0; c < CH; c++) {
        float pc = g_pooled[c*NMAX + s];
        #pragma unroll
        for (int q = 0; q < DD; q++) dd[q] = fmaf(pc, sW[c*DD + q], dd[q]);
    }
    #pragma unroll
    for (int q = 0; q < DD; q++) dd[q] = fmaxf(dd[q], 0.f);
    float* Lr = g_L + (size_t)s*LSTRIDE;
    for (int j = 0; j <= KTOP; j++) {
        float a = 0.f;
        #pragma unroll
        for (int q = 0; q < DD; q++) a = fmaf(dd[q], sD[j*DD + q], a);
        Lr[j] = a;
    }
}

__global__ void kInstance(float* __restrict__ outInst, int N) {
    int w = (blockIdx.x*blockDim.x + threadIdx.x) >> 5;   // one warp per voxel
    int lane = threadIdx.x & 31;
    if (w >= N) return;
    int r = g_seg[g_seg[w]];
    const float* Lr = g_L + (size_t)r*LSTRIDE;
    float* o = outInst + (size_t)w*(KTOP+1);
    for (int t = lane; t < KTOP+1; t += 32) o[t] = Lr[t];
}

// ---------------- launch ----------------
extern "C" void kernel_launch(void* const* d_in, const int* in_sizes, int n_in,
                              void* d_out, int out_size) {
    const int*   coords = (const int*)  d_in[0];
    const float* feats  = (const float*)d_in[1];
    const float* cscore = (const float*)d_in[2];
    const float* offs   = (const float*)d_in[3];
    const float* bg     = (const float*)d_in[4];
    const float* Wd     = (const float*)d_in[5];
    const float* mW     = (const float*)d_in[6];
    const float* mB     = (const float*)d_in[7];
    float* out = (float*)d_out;
    const int N = in_sizes[0] / 4;

    void* p;
    cudaGetSymbolAddress(&p, g_flags);     cudaMemsetAsync(p, 0,    sizeof(int)*CELLS_PAD);
    cudaGetSymbolAddress(&p, g_vcell);     cudaMemsetAsync(p, 0xFF, sizeof(int)*CELLS);
    cudaGetSymbolAddress(&p, g_scoreGrid); cudaMemsetAsync(p, 0,    sizeof(float)*CELLS);
    cudaGetSymbolAddress(&p, g_cnt);       cudaMemsetAsync(p, 0,    sizeof(int)*NMAX);
    cudaGetSymbolAddress(&p, g_sumF);      cudaMemsetAsync(p, 0,    sizeof(float)*CH*NMAX);
    cudaGetSymbolAddress(&p, g_hist);      cudaMemsetAsync(p, 0,    sizeof(int)*NBINS);
    cudaGetSymbolAddress(&p, g_peakCount); cudaMemsetAsync(p, 0,    sizeof(int));
    cudaGetSymbolAddress(&p, g_candCount); cudaMemsetAsync(p, 0,    sizeof(int));

    int nb = (N + 255) / 256;
    kKeys<<<nb, 256>>>(coords, offs, N);
    kBlockScan<<<NBLK, 1024>>>();
    kScanBlkSums<<<1, 512>>>();
    kFinalize<<<(CELLS + 255)/256, 256>>>();
    kSeg<<<nb, 256>>>(N);
    kPerVoxel<<<nb, 256>>>(cscore, N);
    {
        long long tot = (long long)N * CH;
        kAccumF<<<(unsigned)((tot + 255)/256), 256>>>(feats, N);
    }
    kNbr<<<(NMAX + 255)/256, 256>>>();
    {
        dim3 g((NMAX + 255)/256, CH);
        kPooled<<<g, 256>>>();
    }
    kMixer<<<(CELLS + 255)/256, 256>>>(mW, mB, out);
    kPeak<<<(CELLS + 255)/256, 256>>>();
    kChunkSum<<<1024, 256>>>();
    kFindT<<<1, 1024>>>();
    kCompact<<<nb, 256>>>();
    kSelect<<<1, 1024>>>(out + N);
    kPeakDesc<<<KTOP+1, DD>>>(bg, Wd, out + N);
    kFusedL<<<(NMAX + 127)/128, 128>>>(Wd);
    kInstance<<<(N*32 + 255)/256, 256>>>(out + N + KTOP, N);
}